// round 7
// baseline (speedup 1.0000x reference)
#include <cuda_runtime.h>
#include <cuda_bf16.h>
#include <cstdint>

// Problem constants
constexpr int kB = 2, kS = 2048, kH = 32, kHK = 8, kD = 128;
constexpr int kN  = kB * kS;      // 4096
constexpr int kHD = kH * kD;      // 4096
constexpr int kHKD = kHK * kD;    // 1024
constexpr float kScale = 0.08838834764831845f;           // 1/sqrt(128)
constexpr float kSc2   = kScale * 1.4426950408889634f;   // scale * log2(e)

// Tiling: 128 queries per CTA, key tiles of 64, 8 warps
constexpr int BM = 128, BN = 64, NT = 256;
constexpr int NQB = kS / BM;      // 16
constexpr int KP = 136;  // bf16 pitch, conflict-free LDSM (+4 banks/row)
constexpr int VP = 72;

// SMEM element offsets (bf16 elements)
constexpr int eQH  = 0;                    // Q hi [128][136]
constexpr int eQL  = eQH + BM * KP;        // 17408
constexpr int eK0  = eQL + BM * KP;        // K buf0 hi [64][136], lo follows
constexpr int eK0L = eK0 + BN * KP;
constexpr int eK1  = eK0 + 2 * BN * KP;
constexpr int eK1L = eK1 + BN * KP;
constexpr int eV0  = eK1 + 2 * BN * KP;    // V buf0 hi [128][72], lo follows
constexpr int eV0L = eV0 + kD * VP;
constexpr int eV1  = eV0 + 2 * kD * VP;
constexpr int eV1L = eV1 + kD * VP;
constexpr int SMEM_ELEMS = eV1 + 2 * kD * VP;    // 106496
constexpr int SMEM_BYTES = SMEM_ELEMS * 2;       // 212992
static_assert(SMEM_BYTES <= 227328, "smem");

// bf16 hi/lo scratch: K in source layout, V transposed [bh][d][s]
__device__ __nv_bfloat16 g_Khi[(size_t)kN * kHKD];
__device__ __nv_bfloat16 g_Klo[(size_t)kN * kHKD];
__device__ __nv_bfloat16 g_Vthi[(size_t)kN * kHKD];
__device__ __nv_bfloat16 g_Vtlo[(size_t)kN * kHKD];

// ---------------------------------------------------------------------------
// KV-cache output + prep kernels
// ---------------------------------------------------------------------------
__global__ void cache_copy_k_kernel(const float* __restrict__ kc, float* __restrict__ okc) {
    int i = blockIdx.x * blockDim.x + threadIdx.x;
    if (i < kN * kHKD / 4)
        reinterpret_cast<float4*>(okc)[i] = reinterpret_cast<const float4*>(kc)[i];
}
__global__ void cache_copy_v_kernel(const float* __restrict__ vc, float* __restrict__ ovc) {
    int i = blockIdx.x * blockDim.x + threadIdx.x;
    if (i < kN * kHKD / 4)
        reinterpret_cast<float4*>(ovc)[i] = reinterpret_cast<const float4*>(vc)[i];
}
__global__ void cache_scatter_kernel(const float* __restrict__ k, const float* __restrict__ v,
                                     const int* __restrict__ slot,
                                     float* __restrict__ okc, float* __restrict__ ovc) {
    int i = blockIdx.x * blockDim.x + threadIdx.x;
    constexpr int per_row = kHKD / 4;
    if (i < kN * per_row) {
        int n = i / per_row, c = i - n * per_row;
        int s = slot[n];
        if (s >= 0 && s < kN) {
            reinterpret_cast<float4*>(okc)[s * per_row + c] = reinterpret_cast<const float4*>(k)[i];
            reinterpret_cast<float4*>(ovc)[s * per_row + c] = reinterpret_cast<const float4*>(v)[i];
        }
    }
}
__global__ void ksplit_kernel(const float* __restrict__ k) {
    int i = blockIdx.x * blockDim.x + threadIdx.x;
    if (i >= kN * kHKD / 4) return;
    float4 f = reinterpret_cast<const float4*>(k)[i];
    __nv_bfloat162 h0 = __floats2bfloat162_rn(f.x, f.y);
    __nv_bfloat162 h1 = __floats2bfloat162_rn(f.z, f.w);
    __nv_bfloat162 l0 = __floats2bfloat162_rn(f.x - __bfloat162float(h0.x), f.y - __bfloat162float(h0.y));
    __nv_bfloat162 l1 = __floats2bfloat162_rn(f.z - __bfloat162float(h1.x), f.w - __bfloat162float(h1.y));
    reinterpret_cast<__nv_bfloat162*>(g_Khi)[2 * i]     = h0;
    reinterpret_cast<__nv_bfloat162*>(g_Khi)[2 * i + 1] = h1;
    reinterpret_cast<__nv_bfloat162*>(g_Klo)[2 * i]     = l0;
    reinterpret_cast<__nv_bfloat162*>(g_Klo)[2 * i + 1] = l1;
}
__global__ void vtrans_kernel(const float* __restrict__ v) {
    __shared__ __nv_bfloat16 th[32][33];
    __shared__ __nv_bfloat16 tl[32][33];
    int bh = blockIdx.z;
    int d0 = blockIdx.y * 32, s0 = blockIdx.x * 32;
    int b = bh >> 3, hk = bh & 7;
    int tx = threadIdx.x, ty = threadIdx.y;
    float x = v[((size_t)(b * kS + s0 + ty) * kHK + hk) * kD + d0 + tx];
    __nv_bfloat16 h = __float2bfloat16(x);
    th[ty][tx] = h;
    tl[ty][tx] = __float2bfloat16(x - __bfloat162float(h));
    __syncthreads();
    size_t oi = ((size_t)(bh * kD + d0 + ty)) * kS + s0 + tx;
    g_Vthi[oi] = th[tx][ty];
    g_Vtlo[oi] = tl[tx][ty];
}

// ---------------------------------------------------------------------------
// PTX helpers
// ---------------------------------------------------------------------------
__device__ __forceinline__ void mma16816(float* d,
                                         unsigned a0, unsigned a1, unsigned a2, unsigned a3,
                                         unsigned b0, unsigned b1) {
    asm volatile(
        "mma.sync.aligned.m16n8k16.row.col.f32.bf16.bf16.f32 "
        "{%0,%1,%2,%3},{%4,%5,%6,%7},{%8,%9},{%0,%1,%2,%3};\n"
        : "+f"(d[0]), "+f"(d[1]), "+f"(d[2]), "+f"(d[3])
        : "r"(a0), "r"(a1), "r"(a2), "r"(a3), "r"(b0), "r"(b1));
}
__device__ __forceinline__ void ldsm4(unsigned& r0, unsigned& r1,
                                      unsigned& r2, unsigned& r3, unsigned a) {
    asm volatile("ldmatrix.sync.aligned.m8n8.x4.shared.b16 {%0,%1,%2,%3}, [%4];\n"
                 : "=r"(r0), "=r"(r1), "=r"(r2), "=r"(r3) : "r"(a));
}
__device__ __forceinline__ void cp16(unsigned dst, const void* src) {
    asm volatile("cp.async.cg.shared.global [%0], [%1], 16;\n" :: "r"(dst), "l"(src));
}
__device__ __forceinline__ void cp_commit() {
    asm volatile("cp.async.commit_group;" ::: "memory");
}
__device__ __forceinline__ void cp_wait1() {
    asm volatile("cp.async.wait_group 1;" ::: "memory");
}
__device__ __forceinline__ void cp_wait0() {
    asm volatile("cp.async.wait_group 0;" ::: "memory");
}
__device__ __forceinline__ float ex2(float x) {
    float y;
    asm("ex2.approx.f32 %0, %1;" : "=f"(y) : "f"(x));
    return y;
}
__device__ __forceinline__ unsigned pk2(float x, float y) {
    __nv_bfloat162 t = __floats2bfloat162_rn(x, y);
    return *reinterpret_cast<unsigned*>(&t);
}
__device__ __forceinline__ unsigned pk2lo(float x, float y, unsigned hi) {
    __nv_bfloat162 h = *reinterpret_cast<__nv_bfloat162*>(&hi);
    return pk2(x - __bfloat162float(h.x), y - __bfloat162float(h.y));
}

// ---------------------------------------------------------------------------
// Flash attention: bf16x3 mma.sync, static softmax, double-buffered pipeline.
// Grid (16, 32, 2), 256 threads; warp w owns rows [16w, 16w+16).
// ---------------------------------------------------------------------------
__global__ __launch_bounds__(NT, 1)
void attn_kernel(const float* __restrict__ q, float* __restrict__ o) {
    extern __shared__ __nv_bfloat16 sm[];

    const int tid = threadIdx.x;
    const int w = tid >> 5;
    const int lane = tid & 31;
    const int qd = lane >> 2;   // 0..7
    const int qp = lane & 3;    // 0..3
    const int qb = (NQB - 1) - blockIdx.x;   // heavy CTAs first
    const int h = blockIdx.y, b = blockIdx.z;
    const int hk = h >> 2;
    const int bh = b * kHK + hk;
    const int nk = 2 * (qb + 1);
    const int arow = w * 16 + qd;           // local row
    const int rg0 = qb * BM + arow;         // global q row
    const int rg1 = rg0 + 8;

    const uint32_t sb = (uint32_t)__cvta_generic_to_shared(sm);

    // ldmatrix per-lane relative offsets
    const int lrow = ((lane >> 4) << 3) + (lane & 7);
    const int lcol = ((lane >> 3) & 1) << 3;
    const unsigned lK = (unsigned)((lrow * KP + lcol) * 2);
    const unsigned lV = (unsigned)((lrow * VP + lcol) * 2);
    const unsigned uKh[2] = {sb + eK0 * 2 + lK,  sb + eK1 * 2 + lK};
    const unsigned uKl[2] = {sb + eK0L * 2 + lK, sb + eK1L * 2 + lK};
    const unsigned uVh[2] = {sb + eV0 * 2 + lV,  sb + eV1 * 2 + lV};
    const unsigned uVl[2] = {sb + eV0L * 2 + lV, sb + eV1L * 2 + lV};

    const __nv_bfloat16* gKh0 = g_Khi + ((size_t)(b * kS)) * kHKD + hk * kD;
    const __nv_bfloat16* gKl0 = g_Klo + ((size_t)(b * kS)) * kHKD + hk * kD;
    const __nv_bfloat16* gVh0 = g_Vthi + (size_t)bh * kD * kS;
    const __nv_bfloat16* gVl0 = g_Vtlo + (size_t)bh * kD * kS;

    auto prefetch = [&](int kt) {
        const int bw = kt & 1;
        unsigned dKh = sb + (bw ? eK1 : eK0) * 2;
        unsigned dKl = sb + (bw ? eK1L : eK0L) * 2;
        unsigned dVh = sb + (bw ? eV1 : eV0) * 2;
        unsigned dVl = sb + (bw ? eV1L : eV0L) * 2;
        const __nv_bfloat16* kh = gKh0 + (size_t)kt * BN * kHKD;
        const __nv_bfloat16* kl = gKl0 + (size_t)kt * BN * kHKD;
        const __nv_bfloat16* vh = gVh0 + (size_t)kt * BN;
        const __nv_bfloat16* vl = gVl0 + (size_t)kt * BN;
        #pragma unroll
        for (int it = 0; it < 4; ++it) {
            int idx = it * NT + tid;            // 0..1023
            int r = idx >> 4, c = (idx & 15) * 8;
            unsigned doff = (unsigned)((r * KP + c) * 2);
            cp16(dKh + doff, kh + (size_t)r * kHKD + c);
            cp16(dKl + doff, kl + (size_t)r * kHKD + c);
        }
        #pragma unroll
        for (int it = 0; it < 4; ++it) {
            int idx = it * NT + tid;            // 0..1023
            int r = idx >> 3, c = (idx & 7) * 8;
            unsigned doff = (unsigned)((r * VP + c) * 2);
            cp16(dVh + doff, vh + (size_t)r * kS + c);
            cp16(dVl + doff, vl + (size_t)r * kS + c);
        }
        cp_commit();
    };

    prefetch(0);

    // ---- Q load, pre-scale by kSc2, hi/lo split into smem ----
    const float* qbase = q + ((size_t)(b * kS + qb * BM)) * kHD + h * kD;
    #pragma unroll
    for (int it = 0; it < 16; ++it) {
        int idx = it * NT + tid;               // 0..4095 float4s
        int r = idx >> 5, c = (idx & 31) * 4;
        float4 f = *reinterpret_cast<const float4*>(qbase + (size_t)r * kHD + c);
        f.x *= kSc2; f.y *= kSc2; f.z *= kSc2; f.w *= kSc2;
        unsigned h0 = pk2(f.x, f.y), h1 = pk2(f.z, f.w);
        unsigned l0 = pk2lo(f.x, f.y, h0), l1 = pk2lo(f.z, f.w, h1);
        int base = r * KP + c;
        *reinterpret_cast<unsigned*>(&sm[eQH + base])     = h0;
        *reinterpret_cast<unsigned*>(&sm[eQH + base + 2]) = h1;
        *reinterpret_cast<unsigned*>(&sm[eQL + base])     = l0;
        *reinterpret_cast<unsigned*>(&sm[eQL + base + 2]) = l1;
    }
    __syncthreads();

    // ---- hoist Q fragments (loop-invariant) ----
    unsigned ah[8][4], al[8][4];
    #pragma unroll
    for (int c = 0; c < 8; ++c) {
        int k0 = c * 16 + qp * 2;
        ah[c][0] = *reinterpret_cast<const unsigned*>(&sm[eQH +  arow      * KP + k0]);
        ah[c][1] = *reinterpret_cast<const unsigned*>(&sm[eQH + (arow + 8) * KP + k0]);
        ah[c][2] = *reinterpret_cast<const unsigned*>(&sm[eQH +  arow      * KP + k0 + 8]);
        ah[c][3] = *reinterpret_cast<const unsigned*>(&sm[eQH + (arow + 8) * KP + k0 + 8]);
        al[c][0] = *reinterpret_cast<const unsigned*>(&sm[eQL +  arow      * KP + k0]);
        al[c][1] = *reinterpret_cast<const unsigned*>(&sm[eQL + (arow + 8) * KP + k0]);
        al[c][2] = *reinterpret_cast<const unsigned*>(&sm[eQL +  arow      * KP + k0 + 8]);
        al[c][3] = *reinterpret_cast<const unsigned*>(&sm[eQL + (arow + 8) * KP + k0 + 8]);
    }

    float o_[16][4];
    #pragma unroll
    for (int j = 0; j < 16; ++j)
        #pragma unroll
        for (int e = 0; e < 4; ++e) o_[j][e] = 0.f;
    float lr0 = 0.f, lr1 = 0.f;

    for (int kt = 0; kt < nk; ++kt) {
        const int bw = kt & 1;
        if (kt + 1 < nk) { prefetch(kt + 1); cp_wait1(); }
        else             { cp_wait0(); }
        __syncthreads();

        // ---- S = Q K^T (bf16x3) ----
        float s_[8][4];
        #pragma unroll
        for (int j = 0; j < 8; ++j)
            #pragma unroll
            for (int e = 0; e < 4; ++e) s_[j][e] = 0.f;

        #pragma unroll
        for (int c = 0; c < 8; ++c) {
            #pragma unroll
            for (int jp = 0; jp < 4; ++jp) {
                unsigned koff = (unsigned)((jp * 16 * KP + c * 16) * 2);
                unsigned bh0, bh1, bh2, bh3, bl0, bl1, bl2, bl3;
                ldsm4(bh0, bh1, bh2, bh3, uKh[bw] + koff);
                ldsm4(bl0, bl1, bl2, bl3, uKl[bw] + koff);
                mma16816(s_[2 * jp],     ah[c][0], ah[c][1], ah[c][2], ah[c][3], bh0, bh1);
                mma16816(s_[2 * jp],     ah[c][0], ah[c][1], ah[c][2], ah[c][3], bl0, bl1);
                mma16816(s_[2 * jp],     al[c][0], al[c][1], al[c][2], al[c][3], bh0, bh1);
                mma16816(s_[2 * jp + 1], ah[c][0], ah[c][1], ah[c][2], ah[c][3], bh2, bh3);
                mma16816(s_[2 * jp + 1], ah[c][0], ah[c][1], ah[c][2], ah[c][3], bl2, bl3);
                mma16816(s_[2 * jp + 1], al[c][0], al[c][1], al[c][2], al[c][3], bh2, bh3);
            }
        }

        // ---- static softmax: p = 2^s (Q pre-scaled); mask by zeroing ----
        const bool msk = (kt >= 2 * qb);
        #pragma unroll
        for (int j = 0; j < 8; ++j) {
            int cl = kt * BN + j * 8 + qp * 2;
            float p0 = ex2(s_[j][0]);
            float p1 = ex2(s_[j][1]);
            float p2 = ex2(s_[j][2]);
            float p3 = ex2(s_[j][3]);
            if (msk) {
                if (cl     > rg0) p0 = 0.f;
                if (cl + 1 > rg0) p1 = 0.f;
                if (cl     > rg1) p2 = 0.f;
                if (cl + 1 > rg1) p3 = 0.f;
            }
            lr0 += p0 + p1;
            lr1 += p2 + p3;
            s_[j][0] = p0; s_[j][1] = p1; s_[j][2] = p2; s_[j][3] = p3;
        }

        // ---- O += P V (bf16x3) ----
        #pragma unroll
        for (int cc = 0; cc < 4; ++cc) {
            unsigned ph0 = pk2(s_[2 * cc][0], s_[2 * cc][1]);
            unsigned ph1 = pk2(s_[2 * cc][2], s_[2 * cc][3]);
            unsigned ph2 = pk2(s_[2 * cc + 1][0], s_[2 * cc + 1][1]);
            unsigned ph3 = pk2(s_[2 * cc + 1][2], s_[2 * cc + 1][3]);
            unsigned pl0 = pk2lo(s_[2 * cc][0], s_[2 * cc][1], ph0);
            unsigned pl1 = pk2lo(s_[2 * cc][2], s_[2 * cc][3], ph1);
            unsigned pl2 = pk2lo(s_[2 * cc + 1][0], s_[2 * cc + 1][1], ph2);
            unsigned pl3 = pk2lo(s_[2 * cc + 1][2], s_[2 * cc + 1][3], ph3);
            #pragma unroll
            for (int jp = 0; jp < 8; ++jp) {
                unsigned voff = (unsigned)((jp * 16 * VP + cc * 16) * 2);
                unsigned bh0, bh1, bh2, bh3, bl0, bl1, bl2, bl3;
                ldsm4(bh0, bh1, bh2, bh3, uVh[bw] + voff);
                ldsm4(bl0, bl1, bl2, bl3, uVl[bw] + voff);
                mma16816(o_[2 * jp],     ph0, ph1, ph2, ph3, bh0, bh1);
                mma16816(o_[2 * jp],     ph0, ph1, ph2, ph3, bl0, bl1);
                mma16816(o_[2 * jp],     pl0, pl1, pl2, pl3, bh0, bh1);
                mma16816(o_[2 * jp + 1], ph0, ph1, ph2, ph3, bh2, bh3);
                mma16816(o_[2 * jp + 1], ph0, ph1, ph2, ph3, bl2, bl3);
                mma16816(o_[2 * jp + 1], pl0, pl1, pl2, pl3, bh2, bh3);
            }
        }
        __syncthreads();   // all warps done reading bufs before next prefetch
    }

    // ---- final l reduce over qp lanes, normalize, store ----
    lr0 += __shfl_xor_sync(0xffffffffu, lr0, 1);
    lr0 += __shfl_xor_sync(0xffffffffu, lr0, 2);
    lr1 += __shfl_xor_sync(0xffffffffu, lr1, 1);
    lr1 += __shfl_xor_sync(0xffffffffu, lr1, 2);
    float inv0 = 1.0f / lr0, inv1 = 1.0f / lr1;
    float* obase = o + ((size_t)(b * kS + qb * BM + w * 16)) * kHD + h * kD;
    #pragma unroll
    for (int j = 0; j < 16; ++j) {
        int dcol = j * 8 + qp * 2;
        float2 r0 = {o_[j][0] * inv0, o_[j][1] * inv0};
        float2 r1 = {o_[j][2] * inv1, o_[j][3] * inv1};
        *reinterpret_cast<float2*>(obase + (size_t)qd * kHD + dcol)       = r0;
        *reinterpret_cast<float2*>(obase + (size_t)(qd + 8) * kHD + dcol) = r1;
    }
}

// ---------------------------------------------------------------------------
// Launch (attn_kernel is launch #6 so ncu -s 5 -c 1 captures it)
// ---------------------------------------------------------------------------
extern "C" void kernel_launch(void* const* d_in, const int* in_sizes, int n_in,
                              void* d_out, int out_size) {
    const float* q    = (const float*)d_in[0];
    const float* k    = (const float*)d_in[1];
    const float* v    = (const float*)d_in[2];
    const float* kc   = (const float*)d_in[3];
    const float* vc   = (const float*)d_in[4];
    const int*   slot = (const int*)d_in[5];

    float* out    = (float*)d_out;
    float* out_o  = out;
    float* out_kc = out + (size_t)kN * kHD;
    float* out_vc = out_kc + (size_t)kN * kHKD;

    cudaFuncSetAttribute(attn_kernel,
                         cudaFuncAttributeMaxDynamicSharedMemorySize, SMEM_BYTES);

    int n4 = kN * kHKD / 4;
    cache_copy_k_kernel<<<(n4 + 255) / 256, 256>>>(kc, out_kc);
    cache_copy_v_kernel<<<(n4 + 255) / 256, 256>>>(vc, out_vc);
    cache_scatter_kernel<<<(n4 + 255) / 256, 256>>>(k, v, slot, out_kc, out_vc);

    ksplit_kernel<<<(n4 + 255) / 256, 256>>>(k);
    dim3 vg(kS / 32, kD / 32, kB * kHK);
    vtrans_kernel<<<vg, dim3(32, 32)>>>(v);

    dim3 grid(NQB, kH, kB);
    attn_kernel<<<grid, NT, SMEM_BYTES>>>(q, out_o);
}

// round 8
// speedup vs baseline: 1.0444x; 1.0444x over previous
#include <cuda_runtime.h>
#include <cuda_bf16.h>
#include <cstdint>

// Problem constants
constexpr int kB = 2, kS = 2048, kH = 32, kHK = 8, kD = 128;
constexpr int kN  = kB * kS;      // 4096
constexpr int kHD = kH * kD;      // 4096
constexpr int kHKD = kHK * kD;    // 1024
constexpr float kScale = 0.08838834764831845f;           // 1/sqrt(128)
constexpr float kSc2   = kScale * 1.4426950408889634f;   // scale * log2(e)

// Tiling: BM=64 queries/CTA, BN=64 keys/tile, 4 warps, 2 CTAs/SM
constexpr int BM = 64, BN = 64, NT = 128;
constexpr int NQB = kS / BM;      // 32
constexpr int KP = 136;  // bf16 pitch, conflict-free LDSM (+4 banks/row)
constexpr int VP = 72;

// SMEM element offsets (bf16 elements)
constexpr int eK0  = 0;                    // K buf0: hi [64][136], lo follows
constexpr int eK0L = eK0 + BN * KP;
constexpr int eK1  = eK0 + 2 * BN * KP;    // K buf1 (also overlays Q fp32 staging)
constexpr int eK1L = eK1 + BN * KP;
constexpr int eV   = eK1 + 2 * BN * KP;    // V: hi [128][72], lo follows
constexpr int eVL  = eV + kD * VP;
constexpr int SMEM_ELEMS = eV + 2 * kD * VP;   // 53248
constexpr int SMEM_BYTES = SMEM_ELEMS * 2;     // 106496 -> 2 CTAs/SM
static_assert(SMEM_BYTES <= 113664, "smem");
// Q fp32 staging overlay on K1 region: 64 rows x 132 floats = 33792 B <= 34816 B
constexpr int QSP = 132;
static_assert(BM * QSP * 4 <= 2 * BN * KP * 2, "overlay");

// bf16 hi/lo scratch: K in source layout, V transposed [bh][d][s]
__device__ __nv_bfloat16 g_Khi[(size_t)kN * kHKD];
__device__ __nv_bfloat16 g_Klo[(size_t)kN * kHKD];
__device__ __nv_bfloat16 g_Vthi[(size_t)kN * kHKD];
__device__ __nv_bfloat16 g_Vtlo[(size_t)kN * kHKD];

// ---------------------------------------------------------------------------
// KV-cache output + prep kernels
// ---------------------------------------------------------------------------
__global__ void cache_copy_k_kernel(const float* __restrict__ kc, float* __restrict__ okc) {
    int i = blockIdx.x * blockDim.x + threadIdx.x;
    if (i < kN * kHKD / 4)
        reinterpret_cast<float4*>(okc)[i] = reinterpret_cast<const float4*>(kc)[i];
}
__global__ void cache_copy_v_kernel(const float* __restrict__ vc, float* __restrict__ ovc) {
    int i = blockIdx.x * blockDim.x + threadIdx.x;
    if (i < kN * kHKD / 4)
        reinterpret_cast<float4*>(ovc)[i] = reinterpret_cast<const float4*>(vc)[i];
}
__global__ void cache_scatter_kernel(const float* __restrict__ k, const float* __restrict__ v,
                                     const int* __restrict__ slot,
                                     float* __restrict__ okc, float* __restrict__ ovc) {
    int i = blockIdx.x * blockDim.x + threadIdx.x;
    constexpr int per_row = kHKD / 4;
    if (i < kN * per_row) {
        int n = i / per_row, c = i - n * per_row;
        int s = slot[n];
        if (s >= 0 && s < kN) {
            reinterpret_cast<float4*>(okc)[s * per_row + c] = reinterpret_cast<const float4*>(k)[i];
            reinterpret_cast<float4*>(ovc)[s * per_row + c] = reinterpret_cast<const float4*>(v)[i];
        }
    }
}
__global__ void ksplit_kernel(const float* __restrict__ k) {
    int i = blockIdx.x * blockDim.x + threadIdx.x;
    if (i >= kN * kHKD / 4) return;
    float4 f = reinterpret_cast<const float4*>(k)[i];
    __nv_bfloat162 h0 = __floats2bfloat162_rn(f.x, f.y);
    __nv_bfloat162 h1 = __floats2bfloat162_rn(f.z, f.w);
    __nv_bfloat162 l0 = __floats2bfloat162_rn(f.x - __bfloat162float(h0.x), f.y - __bfloat162float(h0.y));
    __nv_bfloat162 l1 = __floats2bfloat162_rn(f.z - __bfloat162float(h1.x), f.w - __bfloat162float(h1.y));
    reinterpret_cast<__nv_bfloat162*>(g_Khi)[2 * i]     = h0;
    reinterpret_cast<__nv_bfloat162*>(g_Khi)[2 * i + 1] = h1;
    reinterpret_cast<__nv_bfloat162*>(g_Klo)[2 * i]     = l0;
    reinterpret_cast<__nv_bfloat162*>(g_Klo)[2 * i + 1] = l1;
}
__global__ void vtrans_kernel(const float* __restrict__ v) {
    __shared__ __nv_bfloat16 th[32][33];
    __shared__ __nv_bfloat16 tl[32][33];
    int bh = blockIdx.z;
    int d0 = blockIdx.y * 32, s0 = blockIdx.x * 32;
    int b = bh >> 3, hk = bh & 7;
    int tx = threadIdx.x, ty = threadIdx.y;
    float x = v[((size_t)(b * kS + s0 + ty) * kHK + hk) * kD + d0 + tx];
    __nv_bfloat16 h = __float2bfloat16(x);
    th[ty][tx] = h;
    tl[ty][tx] = __float2bfloat16(x - __bfloat162float(h));
    __syncthreads();
    size_t oi = ((size_t)(bh * kD + d0 + ty)) * kS + s0 + tx;
    g_Vthi[oi] = th[tx][ty];
    g_Vtlo[oi] = tl[tx][ty];
}

// ---------------------------------------------------------------------------
// PTX helpers
// ---------------------------------------------------------------------------
__device__ __forceinline__ void mma16816(float* d,
                                         unsigned a0, unsigned a1, unsigned a2, unsigned a3,
                                         unsigned b0, unsigned b1) {
    asm volatile(
        "mma.sync.aligned.m16n8k16.row.col.f32.bf16.bf16.f32 "
        "{%0,%1,%2,%3},{%4,%5,%6,%7},{%8,%9},{%0,%1,%2,%3};\n"
        : "+f"(d[0]), "+f"(d[1]), "+f"(d[2]), "+f"(d[3])
        : "r"(a0), "r"(a1), "r"(a2), "r"(a3), "r"(b0), "r"(b1));
}
__device__ __forceinline__ void ldsm4(unsigned& r0, unsigned& r1,
                                      unsigned& r2, unsigned& r3, unsigned a) {
    asm volatile("ldmatrix.sync.aligned.m8n8.x4.shared.b16 {%0,%1,%2,%3}, [%4];\n"
                 : "=r"(r0), "=r"(r1), "=r"(r2), "=r"(r3) : "r"(a));
}
__device__ __forceinline__ void cp16(unsigned dst, const void* src) {
    asm volatile("cp.async.cg.shared.global [%0], [%1], 16;\n" :: "r"(dst), "l"(src));
}
__device__ __forceinline__ void cp_commit() {
    asm volatile("cp.async.commit_group;" ::: "memory");
}
__device__ __forceinline__ void cp_wait1() {
    asm volatile("cp.async.wait_group 1;" ::: "memory");
}
__device__ __forceinline__ float ex2(float x) {
    float y;
    asm("ex2.approx.f32 %0, %1;" : "=f"(y) : "f"(x));
    return y;
}
__device__ __forceinline__ unsigned pk2(float x, float y) {
    __nv_bfloat162 t = __floats2bfloat162_rn(x, y);
    return *reinterpret_cast<unsigned*>(&t);
}
__device__ __forceinline__ unsigned pk2lo(float x, float y, unsigned hi) {
    __nv_bfloat162 h = *reinterpret_cast<__nv_bfloat162*>(&hi);
    return pk2(x - __bfloat162float(h.x), y - __bfloat162float(h.y));
}

// ---------------------------------------------------------------------------
// Flash attention: bf16x3 mma.sync, static softmax, double-K pipeline,
// 2 CTAs/SM. Grid (32, 32, 2), 128 threads; warp w owns rows [16w, 16w+16).
// ---------------------------------------------------------------------------
__global__ __launch_bounds__(NT, 2)
void attn_kernel(const float* __restrict__ q, float* __restrict__ o) {
    extern __shared__ __nv_bfloat16 sm[];
    float* qstage = reinterpret_cast<float*>(sm + eK1);   // overlay on K1

    const int tid = threadIdx.x;
    const int w = tid >> 5;
    const int lane = tid & 31;
    const int qd = lane >> 2;   // 0..7
    const int qp = lane & 3;    // 0..3
    const int qb = (NQB - 1) - blockIdx.x;   // heavy CTAs first
    const int h = blockIdx.y, b = blockIdx.z;
    const int hk = h >> 2;
    const int bh = b * kHK + hk;
    const int nk = qb + 1;
    const int arow = w * 16 + qd;           // local row
    const int rg0 = qb * BM + arow;         // global q row
    const int rg1 = rg0 + 8;

    const uint32_t sb = (uint32_t)__cvta_generic_to_shared(sm);

    // ldmatrix per-lane relative offsets
    const int lrow = ((lane >> 4) << 3) + (lane & 7);
    const int lcol = ((lane >> 3) & 1) << 3;
    const unsigned lK = (unsigned)((lrow * KP + lcol) * 2);
    const unsigned lV = (unsigned)((lrow * VP + lcol) * 2);
    const unsigned uKh[2] = {sb + eK0 * 2 + lK,  sb + eK1 * 2 + lK};
    const unsigned uKl[2] = {sb + eK0L * 2 + lK, sb + eK1L * 2 + lK};
    const unsigned uVh = sb + eV * 2 + lV;
    const unsigned uVl = sb + eVL * 2 + lV;

    const __nv_bfloat16* gKh0 = g_Khi + ((size_t)(b * kS)) * kHKD + hk * kD;
    const __nv_bfloat16* gKl0 = g_Klo + ((size_t)(b * kS)) * kHKD + hk * kD;
    const __nv_bfloat16* gVh0 = g_Vthi + (size_t)bh * kD * kS;
    const __nv_bfloat16* gVl0 = g_Vtlo + (size_t)bh * kD * kS;

    auto prefetchK = [&](int kt) {
        const int bw = kt & 1;
        unsigned dKh = sb + (bw ? eK1 : eK0) * 2;
        unsigned dKl = sb + (bw ? eK1L : eK0L) * 2;
        const __nv_bfloat16* kh = gKh0 + (size_t)kt * BN * kHKD;
        const __nv_bfloat16* kl = gKl0 + (size_t)kt * BN * kHKD;
        #pragma unroll
        for (int it = 0; it < 8; ++it) {
            int idx = it * NT + tid;            // 0..1023
            int r = idx >> 4, c = (idx & 15) * 8;
            unsigned doff = (unsigned)((r * KP + c) * 2);
            cp16(dKh + doff, kh + (size_t)r * kHKD + c);
            cp16(dKl + doff, kl + (size_t)r * kHKD + c);
        }
        cp_commit();
    };
    auto prefetchV = [&](int kt) {
        const __nv_bfloat16* vh = gVh0 + (size_t)kt * BN;
        const __nv_bfloat16* vl = gVl0 + (size_t)kt * BN;
        #pragma unroll
        for (int it = 0; it < 8; ++it) {
            int idx = it * NT + tid;            // 0..1023
            int r = idx >> 3, c = (idx & 7) * 8;
            unsigned doff = (unsigned)((r * VP + c) * 2);
            cp16(sb + eV * 2 + doff,  vh + (size_t)r * kS + c);
            cp16(sb + eVL * 2 + doff, vl + (size_t)r * kS + c);
        }
        cp_commit();
    };

    prefetchK(0);    // group: K(0)
    prefetchV(0);    // group: V(0)

    // ---- Q: stage fp32 (pre-scaled) in overlay, then hoist frags to regs ----
    const float* qbase = q + ((size_t)(b * kS + qb * BM)) * kHD + h * kD;
    #pragma unroll
    for (int it = 0; it < 16; ++it) {
        int idx = it * NT + tid;               // 0..2047 float4s
        int r = idx >> 5, c = (idx & 31) * 4;
        float4 f = *reinterpret_cast<const float4*>(qbase + (size_t)r * kHD + c);
        f.x *= kSc2; f.y *= kSc2; f.z *= kSc2; f.w *= kSc2;
        *reinterpret_cast<float4*>(&qstage[r * QSP + c]) = f;
    }
    __syncthreads();

    unsigned ah[8][4], al[8][4];
    #pragma unroll
    for (int c = 0; c < 8; ++c) {
        int k0 = c * 16 + qp * 2;
        #pragma unroll
        for (int e = 0; e < 4; ++e) {
            int rr = (e & 1) ? arow + 8 : arow;
            int cc = k0 + ((e >> 1) << 3);
            float2 f = *reinterpret_cast<const float2*>(&qstage[rr * QSP + cc]);
            unsigned hi = pk2(f.x, f.y);
            ah[c][e] = hi;
            al[c][e] = pk2lo(f.x, f.y, hi);
        }
    }
    __syncthreads();   // Q overlay dead; K1 region free for prefetch use

    float o_[16][4];
    #pragma unroll
    for (int j = 0; j < 16; ++j)
        #pragma unroll
        for (int e = 0; e < 4; ++e) o_[j][e] = 0.f;
    float lr0 = 0.f, lr1 = 0.f;

    for (int kt = 0; kt < nk; ++kt) {
        const int bw = kt & 1;

        // K(kt) ready (allow V(kt)/next-K pending)
        cp_wait1();
        __syncthreads();

        // ---- S = Q K^T (bf16x3) ----
        float s_[8][4];
        #pragma unroll
        for (int j = 0; j < 8; ++j)
            #pragma unroll
            for (int e = 0; e < 4; ++e) s_[j][e] = 0.f;

        #pragma unroll
        for (int c = 0; c < 8; ++c) {
            #pragma unroll
            for (int jp = 0; jp < 4; ++jp) {
                unsigned koff = (unsigned)((jp * 16 * KP + c * 16) * 2);
                unsigned bh0, bh1, bh2, bh3, bl0, bl1, bl2, bl3;
                ldsm4(bh0, bh1, bh2, bh3, uKh[bw] + koff);
                ldsm4(bl0, bl1, bl2, bl3, uKl[bw] + koff);
                mma16816(s_[2 * jp],     ah[c][0], ah[c][1], ah[c][2], ah[c][3], bh0, bh1);
                mma16816(s_[2 * jp],     ah[c][0], ah[c][1], ah[c][2], ah[c][3], bl0, bl1);
                mma16816(s_[2 * jp],     al[c][0], al[c][1], al[c][2], al[c][3], bh0, bh1);
                mma16816(s_[2 * jp + 1], ah[c][0], ah[c][1], ah[c][2], ah[c][3], bh2, bh3);
                mma16816(s_[2 * jp + 1], ah[c][0], ah[c][1], ah[c][2], ah[c][3], bl2, bl3);
                mma16816(s_[2 * jp + 1], al[c][0], al[c][1], al[c][2], al[c][3], bh2, bh3);
            }
        }
        __syncthreads();               // all warps done reading K(kt)
        if (kt + 1 < nk) prefetchK(kt + 1);   // into other K buf

        // ---- static softmax: p = 2^s (Q pre-scaled); mask by zeroing ----
        const bool msk = (kt == qb);
        #pragma unroll
        for (int j = 0; j < 8; ++j) {
            int cl = kt * BN + j * 8 + qp * 2;
            float p0 = ex2(s_[j][0]);
            float p1 = ex2(s_[j][1]);
            float p2 = ex2(s_[j][2]);
            float p3 = ex2(s_[j][3]);
            if (msk) {
                if (cl     > rg0) p0 = 0.f;
                if (cl + 1 > rg0) p1 = 0.f;
                if (cl     > rg1) p2 = 0.f;
                if (cl + 1 > rg1) p3 = 0.f;
            }
            lr0 += p0 + p1;
            lr1 += p2 + p3;
            s_[j][0] = p0; s_[j][1] = p1; s_[j][2] = p2; s_[j][3] = p3;
        }

        // V(kt) ready (allow K(kt+1) pending)
        cp_wait1();
        __syncthreads();

        // ---- O += P V (bf16x3) ----
        #pragma unroll
        for (int cc = 0; cc < 4; ++cc) {
            unsigned ph0 = pk2(s_[2 * cc][0], s_[2 * cc][1]);
            unsigned ph1 = pk2(s_[2 * cc][2], s_[2 * cc][3]);
            unsigned ph2 = pk2(s_[2 * cc + 1][0], s_[2 * cc + 1][1]);
            unsigned ph3 = pk2(s_[2 * cc + 1][2], s_[2 * cc + 1][3]);
            unsigned pl0 = pk2lo(s_[2 * cc][0], s_[2 * cc][1], ph0);
            unsigned pl1 = pk2lo(s_[2 * cc][2], s_[2 * cc][3], ph1);
            unsigned pl2 = pk2lo(s_[2 * cc + 1][0], s_[2 * cc + 1][1], ph2);
            unsigned pl3 = pk2lo(s_[2 * cc + 1][2], s_[2 * cc + 1][3], ph3);
            #pragma unroll
            for (int jp = 0; jp < 8; ++jp) {
                unsigned voff = (unsigned)((jp * 16 * VP + cc * 16) * 2);
                unsigned bh0, bh1, bh2, bh3, bl0, bl1, bl2, bl3;
                ldsm4(bh0, bh1, bh2, bh3, uVh + voff);
                ldsm4(bl0, bl1, bl2, bl3, uVl + voff);
                mma16816(o_[2 * jp],     ph0, ph1, ph2, ph3, bh0, bh1);
                mma16816(o_[2 * jp],     ph0, ph1, ph2, ph3, bl0, bl1);
                mma16816(o_[2 * jp],     pl0, pl1, pl2, pl3, bh0, bh1);
                mma16816(o_[2 * jp + 1], ph0, ph1, ph2, ph3, bh2, bh3);
                mma16816(o_[2 * jp + 1], ph0, ph1, ph2, ph3, bl2, bl3);
                mma16816(o_[2 * jp + 1], pl0, pl1, pl2, pl3, bh2, bh3);
            }
        }
        __syncthreads();               // all warps done reading V(kt)
        if (kt + 1 < nk) prefetchV(kt + 1);
    }

    // ---- final l reduce over qp lanes, normalize, store ----
    lr0 += __shfl_xor_sync(0xffffffffu, lr0, 1);
    lr0 += __shfl_xor_sync(0xffffffffu, lr0, 2);
    lr1 += __shfl_xor_sync(0xffffffffu, lr1, 1);
    lr1 += __shfl_xor_sync(0xffffffffu, lr1, 2);
    float inv0 = 1.0f / lr0, inv1 = 1.0f / lr1;
    float* obase = o + ((size_t)(b * kS + qb * BM + w * 16)) * kHD + h * kD;
    #pragma unroll
    for (int j = 0; j < 16; ++j) {
        int dcol = j * 8 + qp * 2;
        float2 r0 = {o_[j][0] * inv0, o_[j][1] * inv0};
        float2 r1 = {o_[j][2] * inv1, o_[j][3] * inv1};
        *reinterpret_cast<float2*>(obase + (size_t)qd * kHD + dcol)       = r0;
        *reinterpret_cast<float2*>(obase + (size_t)(qd + 8) * kHD + dcol) = r1;
    }
}

// ---------------------------------------------------------------------------
// Launch (attn_kernel is launch #6 so ncu -s 5 -c 1 captures it)
// ---------------------------------------------------------------------------
extern "C" void kernel_launch(void* const* d_in, const int* in_sizes, int n_in,
                              void* d_out, int out_size) {
    const float* q    = (const float*)d_in[0];
    const float* k    = (const float*)d_in[1];
    const float* v    = (const float*)d_in[2];
    const float* kc   = (const float*)d_in[3];
    const float* vc   = (const float*)d_in[4];
    const int*   slot = (const int*)d_in[5];

    float* out    = (float*)d_out;
    float* out_o  = out;
    float* out_kc = out + (size_t)kN * kHD;
    float* out_vc = out_kc + (size_t)kN * kHKD;

    cudaFuncSetAttribute(attn_kernel,
                         cudaFuncAttributeMaxDynamicSharedMemorySize, SMEM_BYTES);

    int n4 = kN * kHKD / 4;
    cache_copy_k_kernel<<<(n4 + 255) / 256, 256>>>(kc, out_kc);
    cache_copy_v_kernel<<<(n4 + 255) / 256, 256>>>(vc, out_vc);
    cache_scatter_kernel<<<(n4 + 255) / 256, 256>>>(k, v, slot, out_kc, out_vc);

    ksplit_kernel<<<(n4 + 255) / 256, 256>>>(k);
    dim3 vg(kS / 32, kD / 32, kB * kHK);
    vtrans_kernel<<<vg, dim3(32, 32)>>>(v);

    dim3 grid(NQB, kH, kB);
    attn_kernel<<<grid, NT, SMEM_BYTES>>>(q, out_o);
}

// round 9
// speedup vs baseline: 1.4782x; 1.4153x over previous
#include <cuda_runtime.h>
#include <cuda_bf16.h>
#include <cuda_fp16.h>
#include <cstdint>

// Problem constants
constexpr int kB = 2, kS = 2048, kH = 32, kHK = 8, kD = 128;
constexpr int kN  = kB * kS;      // 4096
constexpr int kHD = kH * kD;      // 4096
constexpr int kHKD = kHK * kD;    // 1024
constexpr float kScale = 0.08838834764831845f;           // 1/sqrt(128)
constexpr float kSc2   = kScale * 1.4426950408889634f;   // scale * log2(e)

// Tiling: BM=64 queries/CTA, BN=64 keys/tile, 4 warps, 2 CTAs/SM
constexpr int BM = 64, BN = 64, NT = 128;
constexpr int NQB = kS / BM;      // 32
constexpr int KP = 136;  // fp16 pitch, conflict-free LDSM (+4 banks/row)
constexpr int VP = 72;

// SMEM element offsets (fp16 elements)
constexpr int eK0 = 0;                    // K buf0 [64][136] fp16 (single precision tile)
constexpr int eK1 = eK0 + BN * KP;        // K buf1 (Q fp32 staging overlays K1+V)
constexpr int eV  = eK1 + BN * KP;        // V hi [128][72], lo follows
constexpr int eVL = eV + kD * VP;
constexpr int SMEM_ELEMS = eV + 2 * kD * VP;   // 35840
constexpr int SMEM_BYTES = SMEM_ELEMS * 2;     // 71680 -> 2 CTAs/SM easily
static_assert(SMEM_BYTES <= 113664, "smem");
// Q fp32 staging overlay at eK1: 64 x 132 floats = 33792 B fits in K1+V region
constexpr int QSP = 132;
static_assert(eK1 * 2 + BM * QSP * 4 <= SMEM_BYTES, "overlay");

// fp16 scratch: K single-precision in source layout; V transposed hi/lo [bh][d][s]
__device__ __half g_K16 [(size_t)kN * kHKD];
__device__ __half g_Vthi[(size_t)kN * kHKD];
__device__ __half g_Vtlo[(size_t)kN * kHKD];

// ---------------------------------------------------------------------------
// KV-cache output + prep kernels
// ---------------------------------------------------------------------------
__global__ void cache_copy_k_kernel(const float* __restrict__ kc, float* __restrict__ okc) {
    int i = blockIdx.x * blockDim.x + threadIdx.x;
    if (i < kN * kHKD / 4)
        reinterpret_cast<float4*>(okc)[i] = reinterpret_cast<const float4*>(kc)[i];
}
__global__ void cache_copy_v_kernel(const float* __restrict__ vc, float* __restrict__ ovc) {
    int i = blockIdx.x * blockDim.x + threadIdx.x;
    if (i < kN * kHKD / 4)
        reinterpret_cast<float4*>(ovc)[i] = reinterpret_cast<const float4*>(vc)[i];
}
__global__ void cache_scatter_kernel(const float* __restrict__ k, const float* __restrict__ v,
                                     const int* __restrict__ slot,
                                     float* __restrict__ okc, float* __restrict__ ovc) {
    int i = blockIdx.x * blockDim.x + threadIdx.x;
    constexpr int per_row = kHKD / 4;
    if (i < kN * per_row) {
        int n = i / per_row, c = i - n * per_row;
        int s = slot[n];
        if (s >= 0 && s < kN) {
            reinterpret_cast<float4*>(okc)[s * per_row + c] = reinterpret_cast<const float4*>(k)[i];
            reinterpret_cast<float4*>(ovc)[s * per_row + c] = reinterpret_cast<const float4*>(v)[i];
        }
    }
}
// K -> fp16 (single precision copy)
__global__ void kcvt_kernel(const float* __restrict__ k) {
    int i = blockIdx.x * blockDim.x + threadIdx.x;
    if (i >= kN * kHKD / 4) return;
    float4 f = reinterpret_cast<const float4*>(k)[i];
    reinterpret_cast<__half2*>(g_K16)[2 * i]     = __floats2half2_rn(f.x, f.y);
    reinterpret_cast<__half2*>(g_K16)[2 * i + 1] = __floats2half2_rn(f.z, f.w);
}
// V -> transposed fp16 hi/lo  Vt[bh][d][s]
__global__ void vtrans_kernel(const float* __restrict__ v) {
    __shared__ __half th[32][33];
    __shared__ __half tl[32][33];
    int bh = blockIdx.z;
    int d0 = blockIdx.y * 32, s0 = blockIdx.x * 32;
    int b = bh >> 3, hk = bh & 7;
    int tx = threadIdx.x, ty = threadIdx.y;
    float x = v[((size_t)(b * kS + s0 + ty) * kHK + hk) * kD + d0 + tx];
    __half h = __float2half_rn(x);
    th[ty][tx] = h;
    tl[ty][tx] = __float2half_rn(x - __half2float(h));
    __syncthreads();
    size_t oi = ((size_t)(bh * kD + d0 + ty)) * kS + s0 + tx;
    g_Vthi[oi] = th[tx][ty];
    g_Vtlo[oi] = tl[tx][ty];
}

// ---------------------------------------------------------------------------
// PTX helpers
// ---------------------------------------------------------------------------
__device__ __forceinline__ void mma16816(float* d,
                                         unsigned a0, unsigned a1, unsigned a2, unsigned a3,
                                         unsigned b0, unsigned b1) {
    asm volatile(
        "mma.sync.aligned.m16n8k16.row.col.f32.f16.f16.f32 "
        "{%0,%1,%2,%3},{%4,%5,%6,%7},{%8,%9},{%0,%1,%2,%3};\n"
        : "+f"(d[0]), "+f"(d[1]), "+f"(d[2]), "+f"(d[3])
        : "r"(a0), "r"(a1), "r"(a2), "r"(a3), "r"(b0), "r"(b1));
}
__device__ __forceinline__ void ldsm4(unsigned& r0, unsigned& r1,
                                      unsigned& r2, unsigned& r3, unsigned a) {
    asm volatile("ldmatrix.sync.aligned.m8n8.x4.shared.b16 {%0,%1,%2,%3}, [%4];\n"
                 : "=r"(r0), "=r"(r1), "=r"(r2), "=r"(r3) : "r"(a));
}
__device__ __forceinline__ void cp16(unsigned dst, const void* src) {
    asm volatile("cp.async.cg.shared.global [%0], [%1], 16;\n" :: "r"(dst), "l"(src));
}
__device__ __forceinline__ void cp_commit() {
    asm volatile("cp.async.commit_group;" ::: "memory");
}
__device__ __forceinline__ void cp_wait1() {
    asm volatile("cp.async.wait_group 1;" ::: "memory");
}
__device__ __forceinline__ float ex2(float x) {
    float y;
    asm("ex2.approx.f32 %0, %1;" : "=f"(y) : "f"(x));
    return y;
}
__device__ __forceinline__ unsigned pkh2(float x, float y) {
    __half2 t = __floats2half2_rn(x, y);
    return *reinterpret_cast<unsigned*>(&t);
}
__device__ __forceinline__ unsigned pkh2lo(float x, float y, unsigned hi) {
    __half2 h = *reinterpret_cast<__half2*>(&hi);
    return pkh2(x - __half2float(h.x), y - __half2float(h.y));
}

// ---------------------------------------------------------------------------
// Flash attention: fp16 4-MMA scheme (QK = Qhi.K + Qlo.K ; PV = P.Vhi + P.Vlo),
// static softmax, double-K single-V pipeline, 2 CTAs/SM.
// Grid (32, 32, 2), 128 threads; warp w owns rows [16w, 16w+16).
// ---------------------------------------------------------------------------
__global__ __launch_bounds__(NT, 2)
void attn_kernel(const float* __restrict__ q, float* __restrict__ o) {
    extern __shared__ __half sm[];
    float* qstage = reinterpret_cast<float*>(sm + eK1);   // overlay on K1+V

    const int tid = threadIdx.x;
    const int w = tid >> 5;
    const int lane = tid & 31;
    const int qd = lane >> 2;   // 0..7
    const int qp = lane & 3;    // 0..3
    const int qb = (NQB - 1) - blockIdx.x;   // heavy CTAs first
    const int h = blockIdx.y, b = blockIdx.z;
    const int hk = h >> 2;
    const int bh = b * kHK + hk;
    const int nk = qb + 1;
    const int arow = w * 16 + qd;           // local row
    const int rg0 = qb * BM + arow;         // global q row
    const int rg1 = rg0 + 8;

    const uint32_t sb = (uint32_t)__cvta_generic_to_shared(sm);

    // ldmatrix per-lane relative offsets
    const int lrow = ((lane >> 4) << 3) + (lane & 7);
    const int lcol = ((lane >> 3) & 1) << 3;
    const unsigned lK = (unsigned)((lrow * KP + lcol) * 2);
    const unsigned lV = (unsigned)((lrow * VP + lcol) * 2);
    const unsigned uK[2] = {sb + eK0 * 2 + lK, sb + eK1 * 2 + lK};
    const unsigned uVh = sb + eV * 2 + lV;
    const unsigned uVl = sb + eVL * 2 + lV;

    const __half* gK0  = g_K16 + ((size_t)(b * kS)) * kHKD + hk * kD;
    const __half* gVh0 = g_Vthi + (size_t)bh * kD * kS;
    const __half* gVl0 = g_Vtlo + (size_t)bh * kD * kS;

    auto prefetchK = [&](int kt) {
        unsigned dK = sb + ((kt & 1) ? eK1 : eK0) * 2;
        const __half* kp = gK0 + (size_t)kt * BN * kHKD;
        #pragma unroll
        for (int it = 0; it < 8; ++it) {
            int idx = it * NT + tid;            // 0..1023
            int r = idx >> 4, c = (idx & 15) * 8;
            cp16(dK + (unsigned)((r * KP + c) * 2), kp + (size_t)r * kHKD + c);
        }
        cp_commit();
    };
    auto prefetchV = [&](int kt) {
        const __half* vh = gVh0 + (size_t)kt * BN;
        const __half* vl = gVl0 + (size_t)kt * BN;
        #pragma unroll
        for (int it = 0; it < 8; ++it) {
            int idx = it * NT + tid;            // 0..1023
            int r = idx >> 3, c = (idx & 7) * 8;
            unsigned doff = (unsigned)((r * VP + c) * 2);
            cp16(sb + eV * 2 + doff,  vh + (size_t)r * kS + c);
            cp16(sb + eVL * 2 + doff, vl + (size_t)r * kS + c);
        }
        cp_commit();
    };

    prefetchK(0);    // group: K(0)   (K0 region, not under overlay)

    // ---- Q: stage fp32 (pre-scaled) in overlay, hoist fp16 hi/lo frags ----
    const float* qbase = q + ((size_t)(b * kS + qb * BM)) * kHD + h * kD;
    #pragma unroll
    for (int it = 0; it < 16; ++it) {
        int idx = it * NT + tid;               // 0..2047 float4s
        int r = idx >> 5, c = (idx & 31) * 4;
        float4 f = *reinterpret_cast<const float4*>(qbase + (size_t)r * kHD + c);
        f.x *= kSc2; f.y *= kSc2; f.z *= kSc2; f.w *= kSc2;
        *reinterpret_cast<float4*>(&qstage[r * QSP + c]) = f;
    }
    __syncthreads();

    unsigned ah[8][4], al[8][4];
    #pragma unroll
    for (int c = 0; c < 8; ++c) {
        int k0 = c * 16 + qp * 2;
        #pragma unroll
        for (int e = 0; e < 4; ++e) {
            int rr = (e & 1) ? arow + 8 : arow;
            int cc = k0 + ((e >> 1) << 3);
            float2 f = *reinterpret_cast<const float2*>(&qstage[rr * QSP + cc]);
            unsigned hi = pkh2(f.x, f.y);
            ah[c][e] = hi;
            al[c][e] = pkh2lo(f.x, f.y, hi);
        }
    }
    __syncthreads();   // overlay dead; V region free

    prefetchV(0);      // group: V(0)

    float o_[16][4];
    #pragma unroll
    for (int j = 0; j < 16; ++j)
        #pragma unroll
        for (int e = 0; e < 4; ++e) o_[j][e] = 0.f;
    float lr0 = 0.f, lr1 = 0.f;

    for (int kt = 0; kt < nk; ++kt) {
        const int bw = kt & 1;

        // K(kt) ready (allow V(kt) pending)
        cp_wait1();
        __syncthreads();

        // ---- S = (Qhi + Qlo) . K16 (2 MMAs per fragment pair) ----
        float s_[8][4];
        #pragma unroll
        for (int j = 0; j < 8; ++j)
            #pragma unroll
            for (int e = 0; e < 4; ++e) s_[j][e] = 0.f;

        #pragma unroll
        for (int c = 0; c < 8; ++c) {
            #pragma unroll
            for (int jp = 0; jp < 4; ++jp) {
                unsigned koff = (unsigned)((jp * 16 * KP + c * 16) * 2);
                unsigned b0, b1, b2, b3;
                ldsm4(b0, b1, b2, b3, uK[bw] + koff);
                mma16816(s_[2 * jp],     ah[c][0], ah[c][1], ah[c][2], ah[c][3], b0, b1);
                mma16816(s_[2 * jp],     al[c][0], al[c][1], al[c][2], al[c][3], b0, b1);
                mma16816(s_[2 * jp + 1], ah[c][0], ah[c][1], ah[c][2], ah[c][3], b2, b3);
                mma16816(s_[2 * jp + 1], al[c][0], al[c][1], al[c][2], al[c][3], b2, b3);
            }
        }
        __syncthreads();               // all warps done reading K(kt)
        if (kt + 1 < nk) prefetchK(kt + 1);   // into other K buf

        // ---- static softmax: p = 2^s (Q pre-scaled); mask by zeroing ----
        const bool msk = (kt == qb);
        #pragma unroll
        for (int j = 0; j < 8; ++j) {
            int cl = kt * BN + j * 8 + qp * 2;
            float p0 = ex2(s_[j][0]);
            float p1 = ex2(s_[j][1]);
            float p2 = ex2(s_[j][2]);
            float p3 = ex2(s_[j][3]);
            if (msk) {
                if (cl     > rg0) p0 = 0.f;
                if (cl + 1 > rg0) p1 = 0.f;
                if (cl     > rg1) p2 = 0.f;
                if (cl + 1 > rg1) p3 = 0.f;
            }
            lr0 += p0 + p1;
            lr1 += p2 + p3;
            s_[j][0] = p0; s_[j][1] = p1; s_[j][2] = p2; s_[j][3] = p3;
        }

        // V(kt) ready (allow K(kt+1) pending)
        cp_wait1();
        __syncthreads();

        // ---- O += P16 . (Vhi + Vlo) ----
        #pragma unroll
        for (int cc = 0; cc < 4; ++cc) {
            unsigned p0 = pkh2(s_[2 * cc][0], s_[2 * cc][1]);
            unsigned p1 = pkh2(s_[2 * cc][2], s_[2 * cc][3]);
            unsigned p2 = pkh2(s_[2 * cc + 1][0], s_[2 * cc + 1][1]);
            unsigned p3 = pkh2(s_[2 * cc + 1][2], s_[2 * cc + 1][3]);
            #pragma unroll
            for (int jp = 0; jp < 8; ++jp) {
                unsigned voff = (unsigned)((jp * 16 * VP + cc * 16) * 2);
                unsigned bh0, bh1, bh2, bh3, bl0, bl1, bl2, bl3;
                ldsm4(bh0, bh1, bh2, bh3, uVh + voff);
                ldsm4(bl0, bl1, bl2, bl3, uVl + voff);
                mma16816(o_[2 * jp],     p0, p1, p2, p3, bh0, bh1);
                mma16816(o_[2 * jp],     p0, p1, p2, p3, bl0, bl1);
                mma16816(o_[2 * jp + 1], p0, p1, p2, p3, bh2, bh3);
                mma16816(o_[2 * jp + 1], p0, p1, p2, p3, bl2, bl3);
            }
        }
        __syncthreads();               // all warps done reading V(kt)
        if (kt + 1 < nk) prefetchV(kt + 1);
    }

    // ---- final l reduce over qp lanes, normalize, store ----
    lr0 += __shfl_xor_sync(0xffffffffu, lr0, 1);
    lr0 += __shfl_xor_sync(0xffffffffu, lr0, 2);
    lr1 += __shfl_xor_sync(0xffffffffu, lr1, 1);
    lr1 += __shfl_xor_sync(0xffffffffu, lr1, 2);
    float inv0 = 1.0f / lr0, inv1 = 1.0f / lr1;
    float* obase = o + ((size_t)(b * kS + qb * BM + w * 16)) * kHD + h * kD;
    #pragma unroll
    for (int j = 0; j < 16; ++j) {
        int dcol = j * 8 + qp * 2;
        float2 r0 = {o_[j][0] * inv0, o_[j][1] * inv0};
        float2 r1 = {o_[j][2] * inv1, o_[j][3] * inv1};
        *reinterpret_cast<float2*>(obase + (size_t)qd * kHD + dcol)       = r0;
        *reinterpret_cast<float2*>(obase + (size_t)(qd + 8) * kHD + dcol) = r1;
    }
}

// ---------------------------------------------------------------------------
// Launch (attn_kernel is launch #6 so ncu -s 5 -c 1 captures it)
// ---------------------------------------------------------------------------
extern "C" void kernel_launch(void* const* d_in, const int* in_sizes, int n_in,
                              void* d_out, int out_size) {
    const float* q    = (const float*)d_in[0];
    const float* k    = (const float*)d_in[1];
    const float* v    = (const float*)d_in[2];
    const float* kc   = (const float*)d_in[3];
    const float* vc   = (const float*)d_in[4];
    const int*   slot = (const int*)d_in[5];

    float* out    = (float*)d_out;
    float* out_o  = out;
    float* out_kc = out + (size_t)kN * kHD;
    float* out_vc = out_kc + (size_t)kN * kHKD;

    cudaFuncSetAttribute(attn_kernel,
                         cudaFuncAttributeMaxDynamicSharedMemorySize, SMEM_BYTES);

    int n4 = kN * kHKD / 4;
    cache_copy_k_kernel<<<(n4 + 255) / 256, 256>>>(kc, out_kc);
    cache_copy_v_kernel<<<(n4 + 255) / 256, 256>>>(vc, out_vc);
    cache_scatter_kernel<<<(n4 + 255) / 256, 256>>>(k, v, slot, out_kc, out_vc);

    kcvt_kernel<<<(n4 + 255) / 256, 256>>>(k);
    dim3 vg(kS / 32, kD / 32, kB * kHK);
    vtrans_kernel<<<vg, dim3(32, 32)>>>(v);

    dim3 grid(NQB, kH, kB);
    attn_kernel<<<grid, NT, SMEM_BYTES>>>(q, out_o);
}

// round 10
// speedup vs baseline: 1.9110x; 1.2928x over previous
#include <cuda_runtime.h>
#include <cuda_bf16.h>
#include <cuda_fp16.h>
#include <cstdint>

// Problem constants
constexpr int kB = 2, kS = 2048, kH = 32, kHK = 8, kD = 128;
constexpr int kN  = kB * kS;      // 4096
constexpr int kHD = kH * kD;      // 4096
constexpr int kHKD = kHK * kD;    // 1024
constexpr float kScale = 0.08838834764831845f;           // 1/sqrt(128)
constexpr float kSc2   = kScale * 1.4426950408889634f;   // scale * log2(e)

// Tiling: BM=64 queries/CTA, BN=64 keys/tile, 4 warps, 2 CTAs/SM
constexpr int BM = 64, BN = 64, NT = 128;
constexpr int NQB = kS / BM;      // 32
constexpr int KP = 136;  // fp16 pitch, conflict-free LDSM (+4 banks/row)
constexpr int VP = 72;

// SMEM element offsets (fp16 elements)
constexpr int eK0 = 0;                    // K buf0 [64][136] fp16
constexpr int eK1 = eK0 + BN * KP;        // K buf1 (Q fp32 staging overlays K1+V)
constexpr int eV  = eK1 + BN * KP;        // V [128][72] fp16 (single precision)
constexpr int SMEM_ELEMS = eV + kD * VP;       // 26624
constexpr int SMEM_BYTES = SMEM_ELEMS * 2;     // 53248 -> 2 CTAs/SM
static_assert(SMEM_BYTES <= 113664, "smem");
// Q fp32 staging overlay at eK1: 64 x 132 floats = 33792 B fits in K1+V (35840 B)
constexpr int QSP = 132;
static_assert(eK1 * 2 + BM * QSP * 4 <= SMEM_BYTES, "overlay");

// fp16 scratch: K in source layout; V transposed [bh][d][s]
__device__ __half g_K16[(size_t)kN * kHKD];
__device__ __half g_Vt [(size_t)kN * kHKD];

// ---------------------------------------------------------------------------
// KV-cache output + prep kernels
// ---------------------------------------------------------------------------
__global__ void cache_copy_k_kernel(const float* __restrict__ kc, float* __restrict__ okc) {
    int i = blockIdx.x * blockDim.x + threadIdx.x;
    if (i < kN * kHKD / 4)
        reinterpret_cast<float4*>(okc)[i] = reinterpret_cast<const float4*>(kc)[i];
}
__global__ void cache_copy_v_kernel(const float* __restrict__ vc, float* __restrict__ ovc) {
    int i = blockIdx.x * blockDim.x + threadIdx.x;
    if (i < kN * kHKD / 4)
        reinterpret_cast<float4*>(ovc)[i] = reinterpret_cast<const float4*>(vc)[i];
}
__global__ void cache_scatter_kernel(const float* __restrict__ k, const float* __restrict__ v,
                                     const int* __restrict__ slot,
                                     float* __restrict__ okc, float* __restrict__ ovc) {
    int i = blockIdx.x * blockDim.x + threadIdx.x;
    constexpr int per_row = kHKD / 4;
    if (i < kN * per_row) {
        int n = i / per_row, c = i - n * per_row;
        int s = slot[n];
        if (s >= 0 && s < kN) {
            reinterpret_cast<float4*>(okc)[s * per_row + c] = reinterpret_cast<const float4*>(k)[i];
            reinterpret_cast<float4*>(ovc)[s * per_row + c] = reinterpret_cast<const float4*>(v)[i];
        }
    }
}
// K -> fp16
__global__ void kcvt_kernel(const float* __restrict__ k) {
    int i = blockIdx.x * blockDim.x + threadIdx.x;
    if (i >= kN * kHKD / 4) return;
    float4 f = reinterpret_cast<const float4*>(k)[i];
    reinterpret_cast<__half2*>(g_K16)[2 * i]     = __floats2half2_rn(f.x, f.y);
    reinterpret_cast<__half2*>(g_K16)[2 * i + 1] = __floats2half2_rn(f.z, f.w);
}
// V -> transposed fp16  Vt[bh][d][s]
__global__ void vtrans_kernel(const float* __restrict__ v) {
    __shared__ __half th[32][33];
    int bh = blockIdx.z;
    int d0 = blockIdx.y * 32, s0 = blockIdx.x * 32;
    int b = bh >> 3, hk = bh & 7;
    int tx = threadIdx.x, ty = threadIdx.y;
    float x = v[((size_t)(b * kS + s0 + ty) * kHK + hk) * kD + d0 + tx];
    th[ty][tx] = __float2half_rn(x);
    __syncthreads();
    g_Vt[((size_t)(bh * kD + d0 + ty)) * kS + s0 + tx] = th[tx][ty];
}

// ---------------------------------------------------------------------------
// PTX helpers
// ---------------------------------------------------------------------------
__device__ __forceinline__ void mma16816(float* d,
                                         unsigned a0, unsigned a1, unsigned a2, unsigned a3,
                                         unsigned b0, unsigned b1) {
    asm volatile(
        "mma.sync.aligned.m16n8k16.row.col.f32.f16.f16.f32 "
        "{%0,%1,%2,%3},{%4,%5,%6,%7},{%8,%9},{%0,%1,%2,%3};\n"
        : "+f"(d[0]), "+f"(d[1]), "+f"(d[2]), "+f"(d[3])
        : "r"(a0), "r"(a1), "r"(a2), "r"(a3), "r"(b0), "r"(b1));
}
__device__ __forceinline__ void ldsm4(unsigned& r0, unsigned& r1,
                                      unsigned& r2, unsigned& r3, unsigned a) {
    asm volatile("ldmatrix.sync.aligned.m8n8.x4.shared.b16 {%0,%1,%2,%3}, [%4];\n"
                 : "=r"(r0), "=r"(r1), "=r"(r2), "=r"(r3) : "r"(a));
}
__device__ __forceinline__ void cp16(unsigned dst, const void* src) {
    asm volatile("cp.async.cg.shared.global [%0], [%1], 16;\n" :: "r"(dst), "l"(src));
}
__device__ __forceinline__ void cp_commit() {
    asm volatile("cp.async.commit_group;" ::: "memory");
}
__device__ __forceinline__ void cp_wait1() {
    asm volatile("cp.async.wait_group 1;" ::: "memory");
}
__device__ __forceinline__ float ex2(float x) {
    float y;
    asm("ex2.approx.f32 %0, %1;" : "=f"(y) : "f"(x));
    return y;
}
__device__ __forceinline__ unsigned pkh2(float x, float y) {
    __half2 t = __floats2half2_rn(x, y);
    return *reinterpret_cast<unsigned*>(&t);
}
__device__ __forceinline__ unsigned pkh2lo(float x, float y, unsigned hi) {
    __half2 h = *reinterpret_cast<__half2*>(&hi);
    return pkh2(x - __half2float(h.x), y - __half2float(h.y));
}

// ---------------------------------------------------------------------------
// Flash attention: fp16 3-MMA scheme (QK = Qhi.K + Qlo.K ; PV = P.V16),
// static softmax, double-K single-V pipeline, 2 CTAs/SM.
// Grid (32, 32, 2), 128 threads; warp w owns rows [16w, 16w+16).
// ---------------------------------------------------------------------------
__global__ __launch_bounds__(NT, 2)
void attn_kernel(const float* __restrict__ q, float* __restrict__ o) {
    extern __shared__ __half sm[];
    float* qstage = reinterpret_cast<float*>(sm + eK1);   // overlay on K1+V

    const int tid = threadIdx.x;
    const int w = tid >> 5;
    const int lane = tid & 31;
    const int qd = lane >> 2;   // 0..7
    const int qp = lane & 3;    // 0..3
    const int qb = (NQB - 1) - blockIdx.x;   // heavy CTAs first
    const int h = blockIdx.y, b = blockIdx.z;
    const int hk = h >> 2;
    const int bh = b * kHK + hk;
    const int nk = qb + 1;
    const int arow = w * 16 + qd;           // local row
    const int rg0 = qb * BM + arow;         // global q row
    const int rg1 = rg0 + 8;

    const uint32_t sb = (uint32_t)__cvta_generic_to_shared(sm);

    // ldmatrix per-lane relative offsets
    const int lrow = ((lane >> 4) << 3) + (lane & 7);
    const int lcol = ((lane >> 3) & 1) << 3;
    const unsigned lK = (unsigned)((lrow * KP + lcol) * 2);
    const unsigned lV = (unsigned)((lrow * VP + lcol) * 2);
    const unsigned uK[2] = {sb + eK0 * 2 + lK, sb + eK1 * 2 + lK};
    const unsigned uV = sb + eV * 2 + lV;

    const __half* gK0 = g_K16 + ((size_t)(b * kS)) * kHKD + hk * kD;
    const __half* gV0 = g_Vt + (size_t)bh * kD * kS;

    auto prefetchK = [&](int kt) {
        unsigned dK = sb + ((kt & 1) ? eK1 : eK0) * 2;
        const __half* kp = gK0 + (size_t)kt * BN * kHKD;
        #pragma unroll
        for (int it = 0; it < 8; ++it) {
            int idx = it * NT + tid;            // 0..1023
            int r = idx >> 4, c = (idx & 15) * 8;
            cp16(dK + (unsigned)((r * KP + c) * 2), kp + (size_t)r * kHKD + c);
        }
        cp_commit();
    };
    auto prefetchV = [&](int kt) {
        const __half* vp = gV0 + (size_t)kt * BN;
        #pragma unroll
        for (int it = 0; it < 8; ++it) {
            int idx = it * NT + tid;            // 0..1023
            int r = idx >> 3, c = (idx & 7) * 8;
            cp16(sb + eV * 2 + (unsigned)((r * VP + c) * 2), vp + (size_t)r * kS + c);
        }
        cp_commit();
    };

    prefetchK(0);    // group: K(0)  (K0 region, not under overlay)

    // ---- Q: stage fp32 (pre-scaled) in overlay, hoist fp16 hi/lo frags ----
    const float* qbase = q + ((size_t)(b * kS + qb * BM)) * kHD + h * kD;
    #pragma unroll
    for (int it = 0; it < 16; ++it) {
        int idx = it * NT + tid;               // 0..2047 float4s
        int r = idx >> 5, c = (idx & 31) * 4;
        float4 f = *reinterpret_cast<const float4*>(qbase + (size_t)r * kHD + c);
        f.x *= kSc2; f.y *= kSc2; f.z *= kSc2; f.w *= kSc2;
        *reinterpret_cast<float4*>(&qstage[r * QSP + c]) = f;
    }
    __syncthreads();

    unsigned ah[8][4], al[8][4];
    #pragma unroll
    for (int c = 0; c < 8; ++c) {
        int k0 = c * 16 + qp * 2;
        #pragma unroll
        for (int e = 0; e < 4; ++e) {
            int rr = (e & 1) ? arow + 8 : arow;
            int cc = k0 + ((e >> 1) << 3);
            float2 f = *reinterpret_cast<const float2*>(&qstage[rr * QSP + cc]);
            unsigned hi = pkh2(f.x, f.y);
            ah[c][e] = hi;
            al[c][e] = pkh2lo(f.x, f.y, hi);
        }
    }
    __syncthreads();   // overlay dead; V region free

    prefetchV(0);      // group: V(0)

    float o_[16][4];
    #pragma unroll
    for (int j = 0; j < 16; ++j)
        #pragma unroll
        for (int e = 0; e < 4; ++e) o_[j][e] = 0.f;
    float lr0 = 0.f, lr1 = 0.f;

    for (int kt = 0; kt < nk; ++kt) {
        const int bw = kt & 1;

        // K(kt) ready (allow V(kt) pending)
        cp_wait1();
        __syncthreads();

        // ---- S = (Qhi + Qlo) . K16 ----
        float s_[8][4];
        #pragma unroll
        for (int j = 0; j < 8; ++j)
            #pragma unroll
            for (int e = 0; e < 4; ++e) s_[j][e] = 0.f;

        #pragma unroll
        for (int c = 0; c < 8; ++c) {
            #pragma unroll
            for (int jp = 0; jp < 4; ++jp) {
                unsigned koff = (unsigned)((jp * 16 * KP + c * 16) * 2);
                unsigned b0, b1, b2, b3;
                ldsm4(b0, b1, b2, b3, uK[bw] + koff);
                mma16816(s_[2 * jp],     ah[c][0], ah[c][1], ah[c][2], ah[c][3], b0, b1);
                mma16816(s_[2 * jp],     al[c][0], al[c][1], al[c][2], al[c][3], b0, b1);
                mma16816(s_[2 * jp + 1], ah[c][0], ah[c][1], ah[c][2], ah[c][3], b2, b3);
                mma16816(s_[2 * jp + 1], al[c][0], al[c][1], al[c][2], al[c][3], b2, b3);
            }
        }
        __syncthreads();               // all warps done reading K(kt)
        if (kt + 1 < nk) prefetchK(kt + 1);   // into other K buf

        // ---- static softmax: p = 2^s (Q pre-scaled); mask by zeroing ----
        const bool msk = (kt == qb);
        #pragma unroll
        for (int j = 0; j < 8; ++j) {
            int cl = kt * BN + j * 8 + qp * 2;
            float p0 = ex2(s_[j][0]);
            float p1 = ex2(s_[j][1]);
            float p2 = ex2(s_[j][2]);
            float p3 = ex2(s_[j][3]);
            if (msk) {
                if (cl     > rg0) p0 = 0.f;
                if (cl + 1 > rg0) p1 = 0.f;
                if (cl     > rg1) p2 = 0.f;
                if (cl + 1 > rg1) p3 = 0.f;
            }
            lr0 += p0 + p1;
            lr1 += p2 + p3;
            s_[j][0] = p0; s_[j][1] = p1; s_[j][2] = p2; s_[j][3] = p3;
        }

        // V(kt) ready (allow K(kt+1) pending)
        cp_wait1();
        __syncthreads();

        // ---- O += P16 . V16 ----
        #pragma unroll
        for (int cc = 0; cc < 4; ++cc) {
            unsigned p0 = pkh2(s_[2 * cc][0], s_[2 * cc][1]);
            unsigned p1 = pkh2(s_[2 * cc][2], s_[2 * cc][3]);
            unsigned p2 = pkh2(s_[2 * cc + 1][0], s_[2 * cc + 1][1]);
            unsigned p3 = pkh2(s_[2 * cc + 1][2], s_[2 * cc + 1][3]);
            #pragma unroll
            for (int jp = 0; jp < 8; ++jp) {
                unsigned voff = (unsigned)((jp * 16 * VP + cc * 16) * 2);
                unsigned b0, b1, b2, b3;
                ldsm4(b0, b1, b2, b3, uV + voff);
                mma16816(o_[2 * jp],     p0, p1, p2, p3, b0, b1);
                mma16816(o_[2 * jp + 1], p0, p1, p2, p3, b2, b3);
            }
        }
        __syncthreads();               // all warps done reading V(kt)
        if (kt + 1 < nk) prefetchV(kt + 1);
    }

    // ---- final l reduce over qp lanes, normalize, store ----
    lr0 += __shfl_xor_sync(0xffffffffu, lr0, 1);
    lr0 += __shfl_xor_sync(0xffffffffu, lr0, 2);
    lr1 += __shfl_xor_sync(0xffffffffu, lr1, 1);
    lr1 += __shfl_xor_sync(0xffffffffu, lr1, 2);
    float inv0 = 1.0f / lr0, inv1 = 1.0f / lr1;
    float* obase = o + ((size_t)(b * kS + qb * BM + w * 16)) * kHD + h * kD;
    #pragma unroll
    for (int j = 0; j < 16; ++j) {
        int dcol = j * 8 + qp * 2;
        float2 r0 = {o_[j][0] * inv0, o_[j][1] * inv0};
        float2 r1 = {o_[j][2] * inv1, o_[j][3] * inv1};
        *reinterpret_cast<float2*>(obase + (size_t)qd * kHD + dcol)       = r0;
        *reinterpret_cast<float2*>(obase + (size_t)(qd + 8) * kHD + dcol) = r1;
    }
}

// ---------------------------------------------------------------------------
// Launch (attn_kernel is launch #6 so ncu -s 5 -c 1 captures it)
// ---------------------------------------------------------------------------
extern "C" void kernel_launch(void* const* d_in, const int* in_sizes, int n_in,
                              void* d_out, int out_size) {
    const float* q    = (const float*)d_in[0];
    const float* k    = (const float*)d_in[1];
    const float* v    = (const float*)d_in[2];
    const float* kc   = (const float*)d_in[3];
    const float* vc   = (const float*)d_in[4];
    const int*   slot = (const int*)d_in[5];

    float* out    = (float*)d_out;
    float* out_o  = out;
    float* out_kc = out + (size_t)kN * kHD;
    float* out_vc = out_kc + (size_t)kN * kHKD;

    cudaFuncSetAttribute(attn_kernel,
                         cudaFuncAttributeMaxDynamicSharedMemorySize, SMEM_BYTES);

    int n4 = kN * kHKD / 4;
    cache_copy_k_kernel<<<(n4 + 255) / 256, 256>>>(kc, out_kc);
    cache_copy_v_kernel<<<(n4 + 255) / 256, 256>>>(vc, out_vc);
    cache_scatter_kernel<<<(n4 + 255) / 256, 256>>>(k, v, slot, out_kc, out_vc);

    kcvt_kernel<<<(n4 + 255) / 256, 256>>>(k);
    dim3 vg(kS / 32, kD / 32, kB * kHK);
    vtrans_kernel<<<vg, dim3(32, 32)>>>(v);

    dim3 grid(NQB, kH, kB);
    attn_kernel<<<grid, NT, SMEM_BYTES>>>(q, out_o);
}

// round 11
// speedup vs baseline: 2.4343x; 1.2738x over previous
#include <cuda_runtime.h>
#include <cuda_bf16.h>
#include <cuda_fp16.h>
#include <cstdint>

// Problem constants
constexpr int kB = 2, kS = 2048, kH = 32, kHK = 8, kD = 128;
constexpr int kN  = kB * kS;      // 4096
constexpr int kHD = kH * kD;      // 4096
constexpr int kHKD = kHK * kD;    // 1024
constexpr float kScale = 0.08838834764831845f;           // 1/sqrt(128)
constexpr float kSc2   = kScale * 1.4426950408889634f;   // scale * log2(e)

// Tiling: BM=64 queries/CTA, BN=64 keys/tile, 4 warps, 2 CTAs/SM
constexpr int BM = 64, BN = 64, NT = 128;
constexpr int NQB = kS / BM;      // 32
constexpr int KP = 136;  // fp16 pitch, conflict-free LDSM (+4 banks/row)
constexpr int VP = 72;

// SMEM element offsets (fp16 elements)
constexpr int eK0 = 0;                    // K buf0 [64][136] fp16
constexpr int eK1 = eK0 + BN * KP;        // K buf1 (Q fp32 staging overlays K1+V)
constexpr int eV  = eK1 + BN * KP;        // V [128][72] fp16
constexpr int SMEM_ELEMS = eV + kD * VP;       // 26624
constexpr int SMEM_BYTES = SMEM_ELEMS * 2;     // 53248 -> 2 CTAs/SM
static_assert(SMEM_BYTES <= 113664, "smem");
// Q fp32 staging overlay at eK1: 64 x 132 floats = 33792 B fits in K1+V (35840 B)
constexpr int QSP = 132;
static_assert(eK1 * 2 + BM * QSP * 4 <= SMEM_BYTES, "overlay");

// fp16 scratch: K in source layout; V transposed [bh][d][s]
__device__ __half g_K16[(size_t)kN * kHKD];
__device__ __half g_Vt [(size_t)kN * kHKD];

// ---------------------------------------------------------------------------
// Prep kernels (consolidated: 3 launches)
// ---------------------------------------------------------------------------
__global__ void cache_copy_kernel(const float* __restrict__ kc, const float* __restrict__ vc,
                                  float* __restrict__ okc, float* __restrict__ ovc) {
    int i = blockIdx.x * blockDim.x + threadIdx.x;
    if (i < kN * kHKD / 4) {
        reinterpret_cast<float4*>(okc)[i] = reinterpret_cast<const float4*>(kc)[i];
        reinterpret_cast<float4*>(ovc)[i] = reinterpret_cast<const float4*>(vc)[i];
    }
}
// scatter K/V into caches + convert K to fp16 (k is read once)
__global__ void scatter_cvt_kernel(const float* __restrict__ k, const float* __restrict__ v,
                                   const int* __restrict__ slot,
                                   float* __restrict__ okc, float* __restrict__ ovc) {
    int i = blockIdx.x * blockDim.x + threadIdx.x;
    constexpr int per_row = kHKD / 4;
    if (i >= kN * per_row) return;
    int n = i / per_row, c = i - n * per_row;
    float4 fk = reinterpret_cast<const float4*>(k)[i];
    reinterpret_cast<__half2*>(g_K16)[2 * i]     = __floats2half2_rn(fk.x, fk.y);
    reinterpret_cast<__half2*>(g_K16)[2 * i + 1] = __floats2half2_rn(fk.z, fk.w);
    int s = slot[n];
    if (s >= 0 && s < kN) {
        reinterpret_cast<float4*>(okc)[s * per_row + c] = fk;
        reinterpret_cast<float4*>(ovc)[s * per_row + c] = reinterpret_cast<const float4*>(v)[i];
    }
}
// V -> transposed fp16  Vt[bh][d][s]
__global__ void vtrans_kernel(const float* __restrict__ v) {
    __shared__ __half th[32][33];
    int bh = blockIdx.z;
    int d0 = blockIdx.y * 32, s0 = blockIdx.x * 32;
    int b = bh >> 3, hk = bh & 7;
    int tx = threadIdx.x, ty = threadIdx.y;
    float x = v[((size_t)(b * kS + s0 + ty) * kHK + hk) * kD + d0 + tx];
    th[ty][tx] = __float2half_rn(x);
    __syncthreads();
    g_Vt[((size_t)(bh * kD + d0 + ty)) * kS + s0 + tx] = th[tx][ty];
}

// ---------------------------------------------------------------------------
// PTX helpers
// ---------------------------------------------------------------------------
__device__ __forceinline__ void mma16816(float* d,
                                         unsigned a0, unsigned a1, unsigned a2, unsigned a3,
                                         unsigned b0, unsigned b1) {
    asm volatile(
        "mma.sync.aligned.m16n8k16.row.col.f32.f16.f16.f32 "
        "{%0,%1,%2,%3},{%4,%5,%6,%7},{%8,%9},{%0,%1,%2,%3};\n"
        : "+f"(d[0]), "+f"(d[1]), "+f"(d[2]), "+f"(d[3])
        : "r"(a0), "r"(a1), "r"(a2), "r"(a3), "r"(b0), "r"(b1));
}
__device__ __forceinline__ void ldsm4(unsigned& r0, unsigned& r1,
                                      unsigned& r2, unsigned& r3, unsigned a) {
    asm volatile("ldmatrix.sync.aligned.m8n8.x4.shared.b16 {%0,%1,%2,%3}, [%4];\n"
                 : "=r"(r0), "=r"(r1), "=r"(r2), "=r"(r3) : "r"(a));
}
__device__ __forceinline__ void cp16(unsigned dst, const void* src) {
    asm volatile("cp.async.cg.shared.global [%0], [%1], 16;\n" :: "r"(dst), "l"(src));
}
__device__ __forceinline__ void cp_commit() {
    asm volatile("cp.async.commit_group;" ::: "memory");
}
__device__ __forceinline__ void cp_wait1() {
    asm volatile("cp.async.wait_group 1;" ::: "memory");
}
__device__ __forceinline__ float ex2(float x) {
    float y;
    asm("ex2.approx.f32 %0, %1;" : "=f"(y) : "f"(x));
    return y;
}
__device__ __forceinline__ unsigned pkh2(float x, float y) {
    __half2 t = __floats2half2_rn(x, y);
    return *reinterpret_cast<unsigned*>(&t);
}

// ---------------------------------------------------------------------------
// Flash attention: pure fp16 MMA (QK = Q16.K16 ; PV = P16.V16),
// static softmax, double-K single-V pipeline, 2 CTAs/SM.
// Grid (32, 32, 2), 128 threads; warp w owns rows [16w, 16w+16).
// ---------------------------------------------------------------------------
__global__ __launch_bounds__(NT, 2)
void attn_kernel(const float* __restrict__ q, float* __restrict__ o) {
    extern __shared__ __half sm[];
    float* qstage = reinterpret_cast<float*>(sm + eK1);   // overlay on K1+V

    const int tid = threadIdx.x;
    const int w = tid >> 5;
    const int lane = tid & 31;
    const int qd = lane >> 2;   // 0..7
    const int qp = lane & 3;    // 0..3
    const int qb = (NQB - 1) - blockIdx.x;   // heavy CTAs first
    const int h = blockIdx.y, b = blockIdx.z;
    const int hk = h >> 2;
    const int bh = b * kHK + hk;
    const int nk = qb + 1;
    const int arow = w * 16 + qd;           // local row
    const int rg0 = qb * BM + arow;         // global q row
    const int rg1 = rg0 + 8;

    const uint32_t sb = (uint32_t)__cvta_generic_to_shared(sm);

    // ldmatrix per-lane relative offsets
    const int lrow = ((lane >> 4) << 3) + (lane & 7);
    const int lcol = ((lane >> 3) & 1) << 3;
    const unsigned lK = (unsigned)((lrow * KP + lcol) * 2);
    const unsigned lV = (unsigned)((lrow * VP + lcol) * 2);
    const unsigned uK[2] = {sb + eK0 * 2 + lK, sb + eK1 * 2 + lK};
    const unsigned uV = sb + eV * 2 + lV;

    const __half* gK0 = g_K16 + ((size_t)(b * kS)) * kHKD + hk * kD;
    const __half* gV0 = g_Vt + (size_t)bh * kD * kS;

    auto prefetchK = [&](int kt) {
        unsigned dK = sb + ((kt & 1) ? eK1 : eK0) * 2;
        const __half* kp = gK0 + (size_t)kt * BN * kHKD;
        #pragma unroll
        for (int it = 0; it < 8; ++it) {
            int idx = it * NT + tid;            // 0..1023
            int r = idx >> 4, c = (idx & 15) * 8;
            cp16(dK + (unsigned)((r * KP + c) * 2), kp + (size_t)r * kHKD + c);
        }
        cp_commit();
    };
    auto prefetchV = [&](int kt) {
        const __half* vp = gV0 + (size_t)kt * BN;
        #pragma unroll
        for (int it = 0; it < 8; ++it) {
            int idx = it * NT + tid;            // 0..1023
            int r = idx >> 3, c = (idx & 7) * 8;
            cp16(sb + eV * 2 + (unsigned)((r * VP + c) * 2), vp + (size_t)r * kS + c);
        }
        cp_commit();
    };

    prefetchK(0);    // group: K(0)  (K0 region, not under overlay)

    // ---- Q: stage fp32 (pre-scaled) in overlay, hoist fp16 frags ----
    const float* qbase = q + ((size_t)(b * kS + qb * BM)) * kHD + h * kD;
    #pragma unroll
    for (int it = 0; it < 16; ++it) {
        int idx = it * NT + tid;               // 0..2047 float4s
        int r = idx >> 5, c = (idx & 31) * 4;
        float4 f = *reinterpret_cast<const float4*>(qbase + (size_t)r * kHD + c);
        f.x *= kSc2; f.y *= kSc2; f.z *= kSc2; f.w *= kSc2;
        *reinterpret_cast<float4*>(&qstage[r * QSP + c]) = f;
    }
    __syncthreads();

    unsigned ah[8][4];
    #pragma unroll
    for (int c = 0; c < 8; ++c) {
        int k0 = c * 16 + qp * 2;
        #pragma unroll
        for (int e = 0; e < 4; ++e) {
            int rr = (e & 1) ? arow + 8 : arow;
            int cc = k0 + ((e >> 1) << 3);
            float2 f = *reinterpret_cast<const float2*>(&qstage[rr * QSP + cc]);
            ah[c][e] = pkh2(f.x, f.y);
        }
    }
    __syncthreads();   // overlay dead; V region free

    prefetchV(0);      // group: V(0)

    float o_[16][4];
    #pragma unroll
    for (int j = 0; j < 16; ++j)
        #pragma unroll
        for (int e = 0; e < 4; ++e) o_[j][e] = 0.f;
    float lr0 = 0.f, lr1 = 0.f;

    for (int kt = 0; kt < nk; ++kt) {
        const int bw = kt & 1;

        // K(kt) ready (allow V(kt) pending)
        cp_wait1();
        __syncthreads();

        // ---- S = Q16 . K16 ----
        float s_[8][4];
        #pragma unroll
        for (int j = 0; j < 8; ++j)
            #pragma unroll
            for (int e = 0; e < 4; ++e) s_[j][e] = 0.f;

        #pragma unroll
        for (int c = 0; c < 8; ++c) {
            #pragma unroll
            for (int jp = 0; jp < 4; ++jp) {
                unsigned koff = (unsigned)((jp * 16 * KP + c * 16) * 2);
                unsigned b0, b1, b2, b3;
                ldsm4(b0, b1, b2, b3, uK[bw] + koff);
                mma16816(s_[2 * jp],     ah[c][0], ah[c][1], ah[c][2], ah[c][3], b0, b1);
                mma16816(s_[2 * jp + 1], ah[c][0], ah[c][1], ah[c][2], ah[c][3], b2, b3);
            }
        }
        __syncthreads();               // all warps done reading K(kt)
        if (kt + 1 < nk) prefetchK(kt + 1);   // into other K buf

        // ---- static softmax: p = 2^s (Q pre-scaled); mask by zeroing ----
        const bool msk = (kt == qb);
        #pragma unroll
        for (int j = 0; j < 8; ++j) {
            int cl = kt * BN + j * 8 + qp * 2;
            float p0 = ex2(s_[j][0]);
            float p1 = ex2(s_[j][1]);
            float p2 = ex2(s_[j][2]);
            float p3 = ex2(s_[j][3]);
            if (msk) {
                if (cl     > rg0) p0 = 0.f;
                if (cl + 1 > rg0) p1 = 0.f;
                if (cl     > rg1) p2 = 0.f;
                if (cl + 1 > rg1) p3 = 0.f;
            }
            lr0 += p0 + p1;
            lr1 += p2 + p3;
            s_[j][0] = p0; s_[j][1] = p1; s_[j][2] = p2; s_[j][3] = p3;
        }

        // V(kt) ready (allow K(kt+1) pending)
        cp_wait1();
        __syncthreads();

        // ---- O += P16 . V16 ----
        #pragma unroll
        for (int cc = 0; cc < 4; ++cc) {
            unsigned p0 = pkh2(s_[2 * cc][0], s_[2 * cc][1]);
            unsigned p1 = pkh2(s_[2 * cc][2], s_[2 * cc][3]);
            unsigned p2 = pkh2(s_[2 * cc + 1][0], s_[2 * cc + 1][1]);
            unsigned p3 = pkh2(s_[2 * cc + 1][2], s_[2 * cc + 1][3]);
            #pragma unroll
            for (int jp = 0; jp < 8; ++jp) {
                unsigned voff = (unsigned)((jp * 16 * VP + cc * 16) * 2);
                unsigned b0, b1, b2, b3;
                ldsm4(b0, b1, b2, b3, uV + voff);
                mma16816(o_[2 * jp],     p0, p1, p2, p3, b0, b1);
                mma16816(o_[2 * jp + 1], p0, p1, p2, p3, b2, b3);
            }
        }
        __syncthreads();               // all warps done reading V(kt)
        if (kt + 1 < nk) prefetchV(kt + 1);
    }

    // ---- final l reduce over qp lanes, normalize, store ----
    lr0 += __shfl_xor_sync(0xffffffffu, lr0, 1);
    lr0 += __shfl_xor_sync(0xffffffffu, lr0, 2);
    lr1 += __shfl_xor_sync(0xffffffffu, lr1, 1);
    lr1 += __shfl_xor_sync(0xffffffffu, lr1, 2);
    float inv0 = 1.0f / lr0, inv1 = 1.0f / lr1;
    float* obase = o + ((size_t)(b * kS + qb * BM + w * 16)) * kHD + h * kD;
    #pragma unroll
    for (int j = 0; j < 16; ++j) {
        int dcol = j * 8 + qp * 2;
        float2 r0 = {o_[j][0] * inv0, o_[j][1] * inv0};
        float2 r1 = {o_[j][2] * inv1, o_[j][3] * inv1};
        *reinterpret_cast<float2*>(obase + (size_t)qd * kHD + dcol)       = r0;
        *reinterpret_cast<float2*>(obase + (size_t)(qd + 8) * kHD + dcol) = r1;
    }
}

// ---------------------------------------------------------------------------
// Launch
// ---------------------------------------------------------------------------
extern "C" void kernel_launch(void* const* d_in, const int* in_sizes, int n_in,
                              void* d_out, int out_size) {
    const float* q    = (const float*)d_in[0];
    const float* k    = (const float*)d_in[1];
    const float* v    = (const float*)d_in[2];
    const float* kc   = (const float*)d_in[3];
    const float* vc   = (const float*)d_in[4];
    const int*   slot = (const int*)d_in[5];

    float* out    = (float*)d_out;
    float* out_o  = out;
    float* out_kc = out + (size_t)kN * kHD;
    float* out_vc = out_kc + (size_t)kN * kHKD;

    cudaFuncSetAttribute(attn_kernel,
                         cudaFuncAttributeMaxDynamicSharedMemorySize, SMEM_BYTES);

    int n4 = kN * kHKD / 4;
    cache_copy_kernel<<<(n4 + 255) / 256, 256>>>(kc, vc, out_kc, out_vc);
    scatter_cvt_kernel<<<(n4 + 255) / 256, 256>>>(k, v, slot, out_kc, out_vc);
    dim3 vg(kS / 32, kD / 32, kB * kHK);
    vtrans_kernel<<<vg, dim3(32, 32)>>>(v);

    dim3 grid(NQB, kH, kB);
    attn_kernel<<<grid, NT, SMEM_BYTES>>>(q, out_o);
}